// round 12
// baseline (speedup 1.0000x reference)
#include <cuda_runtime.h>

// snnTorch Leaky SNN scan (v7 — DEPTH 16 ring, unroll matched to DEPTH):
//   reset_t = H(mem_{t-1} - 1)
//   mem_t   = 0.5*mem_{t-1} + x_t - reset_t
//   spk_t   = H(mem_t - 1)
// v6 hung: DEPTH=16 with unroll 8 made buf indices non-static
// ((8j+i)&15 depends on j) -> local-memory demotion -> ~100x slowdown,
// harness timeout. Invariant restored: unroll == DEPTH so t&15 == i is
// a literal per slot and the ring stays in registers.
// v5 baseline: 45.5us, DRAM 73%. This is the (corrected) probe of
// whether deeper MLP buys anything or 73% is the mixed r/w ceiling.

#define T_STEPS 128
#define DEPTH   16         // prefetch distance; MUST equal unroll factor

__global__ __launch_bounds__(64) void snn_leaky_kernel(
    const float4* __restrict__ x, float4* __restrict__ out, int nv)
{
    const int tid = blockIdx.x * blockDim.x + threadIdx.x;
    if (tid >= nv) return;

    const float4* xp = x + tid;
    float4*       op = out + tid;

    // Prime the pipeline: 16 independent LDG.E.128 in flight, guaranteed.
    float4 buf[DEPTH];
    #pragma unroll
    for (int i = 0; i < DEPTH; i++)
        buf[i] = __ldcs(xp + (size_t)i * nv);

    float4 mem = make_float4(0.f, 0.f, 0.f, 0.f);

    #pragma unroll 16   // == DEPTH: keeps buf[t & 15] a compile-time index
    for (int t = 0; t < T_STEPS; t++) {
        const float4 cur = buf[t & (DEPTH - 1)];

        // Refill the ring slot immediately -> keeps 16 loads outstanding.
        const int tn = t + DEPTH;
        if (tn < T_STEPS)
            buf[t & (DEPTH - 1)] = __ldcs(xp + (size_t)tn * nv);

        float4 spk;
        {
            const float reset = (mem.x > 1.0f) ? 1.0f : 0.0f;
            mem.x = 0.5f * mem.x + cur.x - reset;
            spk.x = (mem.x > 1.0f) ? 1.0f : 0.0f;
        }
        {
            const float reset = (mem.y > 1.0f) ? 1.0f : 0.0f;
            mem.y = 0.5f * mem.y + cur.y - reset;
            spk.y = (mem.y > 1.0f) ? 1.0f : 0.0f;
        }
        {
            const float reset = (mem.z > 1.0f) ? 1.0f : 0.0f;
            mem.z = 0.5f * mem.z + cur.z - reset;
            spk.z = (mem.z > 1.0f) ? 1.0f : 0.0f;
        }
        {
            const float reset = (mem.w > 1.0f) ? 1.0f : 0.0f;
            mem.w = 0.5f * mem.w + cur.w - reset;
            spk.w = (mem.w > 1.0f) ? 1.0f : 0.0f;
        }

        // Streaming store: output never re-read by this kernel.
        __stcs(op + (size_t)t * nv, spk);
    }
}

extern "C" void kernel_launch(void* const* d_in, const int* in_sizes, int n_in,
                              void* d_out, int out_size)
{
    (void)n_in; (void)out_size;
    const float4* x = (const float4*)d_in[0];
    float4*       o = (float4*)d_out;

    // total elements = T * B * N; B*N divisible by 4 (N = 4096 nominal)
    const int bn = in_sizes[0] / T_STEPS;   // neurons per timestep
    const int nv = bn / 4;                  // float4 lanes per timestep

    const int threads = 64;                 // fine-grained CTAs
    const int blocks  = (nv + threads - 1) / threads;
    snn_leaky_kernel<<<blocks, threads>>>(x, o, nv);
}